// round 2
// baseline (speedup 1.0000x reference)
#include <cuda_runtime.h>

// SSIM loss: X,Y (4,64,256,256) fp32, 7x7 valid box filter, loss scalar -> out[4].
// loss = 1 - mean(S) over all (B,D,250,250) pixels.

#define WIN 7
#define HH 256
#define WW 256
#define OUTD 250
#define NSLICES 256          // B*D = 4*64
#define BANDS 10             // 10 bands * 25 rows = 250 output rows
#define RPB 25
#define WPC 4                // warps per CTA
#define NCTA ((NSLICES * BANDS) / WPC)   // 640
#define NPIX 16000000.0      // 4*64*250*250

__device__ double g_acc;

// FMA-only reciprocal (avoids MUFU.RCP throughput wall: 0.5/cyc/SM).
// Bit-hack seed (~few % rel err) + 3 Newton iterations -> ~fp32-exact.
__device__ __forceinline__ float fast_rcp(float d) {
    float r = __int_as_float(0x7EF311C3u - __float_as_int(d));
    r = r * fmaf(-d, r, 2.0f);
    r = r * fmaf(-d, r, 2.0f);
    r = r * fmaf(-d, r, 2.0f);
    return r;
}

// Load 16 consecutive floats (4x float4) starting at col0 of row pointer p.
// Out-of-range chunks (col >= 256) become zeros (consumed only by masked outputs).
__device__ __forceinline__ void load16(const float* __restrict__ p, int col0, float v[16]) {
#pragma unroll
    for (int k = 0; k < 4; k++) {
        int col = col0 + 4 * k;
        float4 a = make_float4(0.f, 0.f, 0.f, 0.f);
        if (col < WW) a = *reinterpret_cast<const float4*>(p + col);
        v[4 * k + 0] = a.x; v[4 * k + 1] = a.y;
        v[4 * k + 2] = a.z; v[4 * k + 3] = a.w;
    }
}

__global__ void ssim_zero_kernel() {
    g_acc = 0.0;
}

__global__ void __launch_bounds__(32 * WPC, 3) ssim_main_kernel(
        const float* __restrict__ X, const float* __restrict__ Y) {
    const int warp  = blockIdx.x * WPC + (threadIdx.x >> 5);
    const int lane  = threadIdx.x & 31;
    const int slice = warp / BANDS;
    const int band  = warp % BANDS;

    const float* xs = X + (size_t)slice * (HH * WW);
    const float* ys = Y + (size_t)slice * (HH * WW);
    const int cb = lane * 8;          // first output column owned by this lane

    // Vertical sliding 7-row sums for 14 columns (cols cb .. cb+13), in registers.
    float sx[14], sy[14], sq[14], sxy[14];
#pragma unroll
    for (int c = 0; c < 14; c++) { sx[c] = 0.f; sy[c] = 0.f; sq[c] = 0.f; sxy[c] = 0.f; }

    const int r0 = band * RPB;

    // Prologue: accumulate rows r0 .. r0+5 (6 rows).
    for (int r = r0; r < r0 + WIN - 1; ++r) {
        float xv[16], yv[16];
        load16(xs + r * WW, cb, xv);
        load16(ys + r * WW, cb, yv);
#pragma unroll
        for (int c = 0; c < 14; c++) {
            float x = xv[c], y = yv[c];
            sx[c] += x; sy[c] += y;
            sq[c]  = fmaf(x, x, sq[c]);
            sq[c]  = fmaf(y, y, sq[c]);
            sxy[c] = fmaf(x, y, sxy[c]);
        }
    }

    const float C1    = 0.01f * 0.01f;
    const float C2    = 0.03f * 0.03f;
    const float inv49 = 1.0f / 49.0f;
    const float covn  = 49.0f / 48.0f;
    const float covn2 = 2.0f * 49.0f / 48.0f;

    float acc = 0.f;

    for (int i = r0; i < r0 + RPB; ++i) {
        float xn[16], yn[16], xo[16], yo[16];
        load16(xs + (i + 6) * WW, cb, xn);       // entering row i+6
        load16(ys + (i + 6) * WW, cb, yn);
        load16(xs + i * WW, cb, xo);             // leaving row i (L1/L2 hit)
        load16(ys + i * WW, cb, yo);

        // Add entering row: window now holds rows i .. i+6 (7 rows).
#pragma unroll
        for (int c = 0; c < 14; c++) {
            sx[c]  += xn[c];
            sy[c]  += yn[c];
            sq[c]   = fmaf(xn[c], xn[c], sq[c]);
            sq[c]   = fmaf(yn[c], yn[c], sq[c]);
            sxy[c]  = fmaf(xn[c], yn[c], sxy[c]);
        }

        // Horizontal sliding 7-sum over the 14 column sums -> 8 outputs.
        float hx = 0.f, hy = 0.f, hq = 0.f, hxy = 0.f;
#pragma unroll
        for (int c = 0; c < 6; c++) { hx += sx[c]; hy += sy[c]; hq += sq[c]; hxy += sxy[c]; }

#pragma unroll
        for (int j = 0; j < 8; j++) {
            hx += sx[j + 6]; hy += sy[j + 6]; hq += sq[j + 6]; hxy += sxy[j + 6];
            if (cb + j < OUTD) {
                float ux   = hx  * inv49;
                float uy   = hy  * inv49;
                float uq   = hq  * inv49;   // uxx + uyy
                float uxy  = hxy * inv49;
                float uxuy = ux * uy;
                float A1   = fmaf(2.f, uxuy, C1);
                float s2   = fmaf(ux, ux, uy * uy);      // ux^2 + uy^2
                float B1   = s2 + C1;
                float A2   = fmaf(covn2, uxy - uxuy, C2); // 2*vxy + C2
                float B2   = fmaf(covn,  uq  - s2,   C2); // vx+vy + C2
                float num  = A1 * A2;
                float den  = B1 * B2;
                acc = fmaf(num, fast_rcp(den), acc);
            }
            hx -= sx[j]; hy -= sy[j]; hq -= sq[j]; hxy -= sxy[j];
        }

        // Subtract leaving row i AFTER the outputs: window becomes rows i+1 .. i+6.
#pragma unroll
        for (int c = 0; c < 14; c++) {
            sx[c]  -= xo[c];
            sy[c]  -= yo[c];
            sq[c]   = fmaf(xo[c], -xo[c], sq[c]);
            sq[c]   = fmaf(yo[c], -yo[c], sq[c]);
            sxy[c]  = fmaf(xo[c], -yo[c], sxy[c]);
        }
    }

    // Reduce: warp shuffle -> CTA smem -> one double atomic per CTA.
#pragma unroll
    for (int o = 16; o > 0; o >>= 1)
        acc += __shfl_down_sync(0xFFFFFFFFu, acc, o);

    __shared__ float wsum[WPC];
    if (lane == 0) wsum[threadIdx.x >> 5] = acc;
    __syncthreads();
    if (threadIdx.x == 0) {
        float s = 0.f;
#pragma unroll
        for (int w = 0; w < WPC; w++) s += wsum[w];
        atomicAdd(&g_acc, (double)s);
    }
}

__global__ void ssim_finalize_kernel(float* __restrict__ out, int out_size) {
    float loss = (float)(1.0 - g_acc * (1.0 / NPIX));
    int t = threadIdx.x;
    if (t < out_size) out[t] = loss;
}

extern "C" void kernel_launch(void* const* d_in, const int* in_sizes, int n_in,
                              void* d_out, int out_size) {
    // Pick X, Y by element count (4*64*256*256); skip w (49 elements, constant 1/49).
    const float* X = nullptr;
    const float* Y = nullptr;
    for (int i = 0; i < n_in; i++) {
        if (in_sizes[i] == 4 * 64 * 256 * 256) {
            if (!X) X = (const float*)d_in[i];
            else if (!Y) Y = (const float*)d_in[i];
        }
    }

    ssim_zero_kernel<<<1, 1>>>();
    ssim_main_kernel<<<NCTA, 32 * WPC>>>(X, Y);
    ssim_finalize_kernel<<<1, 32>>>((float*)d_out, out_size);
}

// round 3
// speedup vs baseline: 1.0967x; 1.0967x over previous
#include <cuda_runtime.h>

// SSIM loss: X,Y (4,64,256,256) fp32, 7x7 valid box, loss scalar -> out[4].
// loss = 1 - mean(S) over all (B*D, 250, 250) pixels.
//
// Scale-folded formula (49^4 cancels): with H* = raw 7x7 window sums,
//   A1 = 2*Hx*Hy + c1              c1 = 49^2 * 1e-4
//   A2 = covn2*(49*Hxy - Hx*Hy) + c2    c2 = 49^2 * 9e-4, covn2 = 2*49/48
//   B1 = Hx^2 + Hy^2 + c1
//   B2 = covn*(49*Hq - Hx^2 - Hy^2) + c2    (Hq = window sum of x^2+y^2)
//   S  = A1*A2 / (B1*B2)

#define WIN 7
#define HH 256
#define WW 256
#define OUTD 250
#define NSLICES 256          // B*D
#define BANDS 5              // 5 bands * 50 rows = 250 output rows
#define RPB 50
#define NCTA (NSLICES * BANDS)   // 1280 single-warp CTAs
#define NSLOT 64
#define NPIX 16000000.0

__device__ double g_slots[NSLOT];   // zero-initialized; finalize self-resets

typedef unsigned long long u64;

// ---- f32x2 packed helpers (fma pipe, 2 floats per issue slot) ----
__device__ __forceinline__ u64 pk(float lo, float hi) {
    u64 r; asm("mov.b64 %0, {%1,%2};" : "=l"(r) : "f"(lo), "f"(hi)); return r;
}
__device__ __forceinline__ void upk(u64 v, float& lo, float& hi) {
    asm("mov.b64 {%0,%1}, %2;" : "=f"(lo), "=f"(hi) : "l"(v));
}
__device__ __forceinline__ u64 f2add(u64 a, u64 b) {
    u64 d; asm("add.rn.f32x2 %0,%1,%2;" : "=l"(d) : "l"(a), "l"(b)); return d;
}
__device__ __forceinline__ u64 f2mul(u64 a, u64 b) {
    u64 d; asm("mul.rn.f32x2 %0,%1,%2;" : "=l"(d) : "l"(a), "l"(b)); return d;
}
__device__ __forceinline__ u64 f2fma(u64 a, u64 b, u64 c) {
    u64 d; asm("fma.rn.f32x2 %0,%1,%2,%3;" : "=l"(d) : "l"(a), "l"(b), "l"(c)); return d;
}

// Load 16 consecutive floats (4x float4) starting at col0 of row pointer p.
// Chunks with col >= 256 become zeros (consumed only by masked outputs).
__device__ __forceinline__ void load16(const float* __restrict__ p, int col0, float v[16]) {
#pragma unroll
    for (int k = 0; k < 4; k++) {
        int col = col0 + 4 * k;
        float4 a = make_float4(0.f, 0.f, 0.f, 0.f);
        if (col < WW) a = *reinterpret_cast<const float4*>(p + col);
        v[4 * k + 0] = a.x; v[4 * k + 1] = a.y;
        v[4 * k + 2] = a.z; v[4 * k + 3] = a.w;
    }
}

__global__ void __launch_bounds__(32) ssim_main_kernel(
        const float* __restrict__ X, const float* __restrict__ Y) {
    const int b     = blockIdx.x;
    const int lane  = threadIdx.x;
    const int slice = b / BANDS;
    const int band  = b % BANDS;

    const float* xs = X + (size_t)slice * (HH * WW);
    const float* ys = Y + (size_t)slice * (HH * WW);
    const int cb = lane * 8;          // first output column owned by this lane

    // Packed constants
    const float c1f    = 49.0f * 49.0f * 1e-4f;       // 0.2401
    const float c2f    = 49.0f * 49.0f * 9e-4f;       // 2.1609
    const float covn   = 49.0f / 48.0f;
    const u64 C1V   = pk(c1f, c1f);
    const u64 C2V   = pk(c2f, c2f);
    const u64 TWOV  = pk(2.0f, 2.0f);
    const u64 NCV2  = pk(-2.0f * covn, -2.0f * covn);     // -covn2
    const u64 CV2_49= pk(98.0f * covn, 98.0f * covn);     // 49*covn2
    const u64 NCV   = pk(-covn, -covn);
    const u64 CV_49 = pk(49.0f * covn, 49.0f * covn);

    // Validity masks per output pair (only lane 31 has invalid columns)
    u64 mask[4];
#pragma unroll
    for (int jp = 0; jp < 4; jp++) {
        float m0 = (cb + 2 * jp     < OUTD) ? 1.0f : 0.0f;
        float m1 = (cb + 2 * jp + 1 < OUTD) ? 1.0f : 0.0f;
        mask[jp] = pk(m0, m1);
    }

    // Vertical sliding 7-row sums for 14 columns, in registers.
    float sx[14], sy[14], sq[14], sxy[14];
#pragma unroll
    for (int c = 0; c < 14; c++) { sx[c] = 0.f; sy[c] = 0.f; sq[c] = 0.f; sxy[c] = 0.f; }

    const int r0 = band * RPB;

    // Prologue: rows r0 .. r0+5
    for (int r = r0; r < r0 + WIN - 1; ++r) {
        float xv[16], yv[16];
        load16(xs + r * WW, cb, xv);
        load16(ys + r * WW, cb, yv);
#pragma unroll
        for (int c = 0; c < 14; c++) {
            float x = xv[c], y = yv[c];
            sx[c] += x; sy[c] += y;
            sq[c]  = fmaf(x, x, sq[c]);
            sq[c]  = fmaf(y, y, sq[c]);
            sxy[c] = fmaf(x, y, sxy[c]);
        }
    }

    u64 acc2 = pk(0.f, 0.f);

    for (int i = r0; i < r0 + RPB; ++i) {
        float xn[16], yn[16], xo[16], yo[16];
        load16(xs + (i + 6) * WW, cb, xn);       // entering row i+6
        load16(ys + (i + 6) * WW, cb, yn);
        load16(xs + i * WW, cb, xo);             // leaving row i
        load16(ys + i * WW, cb, yo);

        // Add entering row: window = rows i .. i+6.
#pragma unroll
        for (int c = 0; c < 14; c++) {
            sx[c]  += xn[c];
            sy[c]  += yn[c];
            sq[c]   = fmaf(xn[c], xn[c], sq[c]);
            sq[c]   = fmaf(yn[c], yn[c], sq[c]);
            sxy[c]  = fmaf(xn[c], yn[c], sxy[c]);
        }

        // Horizontal sliding 7-sum, processing outputs in packed pairs.
        float hx = 0.f, hy = 0.f, hq = 0.f, hxy = 0.f;
#pragma unroll
        for (int c = 0; c < 6; c++) { hx += sx[c]; hy += sy[c]; hq += sq[c]; hxy += sxy[c]; }

#pragma unroll
        for (int jp = 0; jp < 4; jp++) {
            const int j0 = 2 * jp;
            // pixel j0: cols j0..j0+6
            hx += sx[j0 + 6]; hy += sy[j0 + 6]; hq += sq[j0 + 6]; hxy += sxy[j0 + 6];
            const float hx0 = hx, hy0 = hy, hq0 = hq, hxy0 = hxy;
            // pixel j0+1: cols j0+1..j0+7
            hx += sx[j0 + 7] - sx[j0];
            hy += sy[j0 + 7] - sy[j0];
            hq += sq[j0 + 7] - sq[j0];
            hxy += sxy[j0 + 7] - sxy[j0];

            u64 Hx  = pk(hx0,  hx);
            u64 Hy  = pk(hy0,  hy);
            u64 Hq  = pk(hq0,  hq);
            u64 Hxy = pk(hxy0, hxy);

            u64 P   = f2mul(Hx, Hy);                 // Hx*Hy
            u64 A1  = f2fma(TWOV,   P,  C1V);        // 2P + c1
            u64 T   = f2fma(NCV2,   P,  C2V);        // -covn2*P + c2
            u64 A2  = f2fma(CV2_49, Hxy, T);         // 49covn2*Hxy + T
            u64 Q   = f2mul(Hy, Hy);
            u64 S2  = f2fma(Hx, Hx, Q);              // Hx^2 + Hy^2
            u64 B1  = f2add(S2, C1V);
            u64 U   = f2fma(NCV,   S2, C2V);         // -covn*S2 + c2
            u64 B2  = f2fma(CV_49, Hq, U);           // 49covn*Hq + U
            u64 num = f2mul(A1, A2);
            num     = f2mul(num, mask[jp]);          // zero invalid pixels
            u64 den = f2mul(B1, B2);                 // > 0 always (Cauchy-Schwarz)

            // Packed Newton reciprocal (2 iters; seed err ~3e-2 -> ~1e-6)
            float dl, dh; upk(den, dl, dh);
            unsigned bl = __float_as_uint(dl), bh = __float_as_uint(dh);
            u64 r  = pk(__uint_as_float(0x7EF311C3u - bl),
                        __uint_as_float(0x7EF311C3u - bh));
            u64 nd = pk(__uint_as_float(bl ^ 0x80000000u),
                        __uint_as_float(bh ^ 0x80000000u));
            u64 t  = f2fma(nd, r, TWOV); r = f2mul(r, t);
            t      = f2fma(nd, r, TWOV); r = f2mul(r, t);

            acc2 = f2fma(num, r, acc2);

            // shift window to cols j0+2.. for next pair
            hx -= sx[j0 + 1]; hy -= sy[j0 + 1]; hq -= sq[j0 + 1]; hxy -= sxy[j0 + 1];
        }

        // Subtract leaving row i: window becomes rows i+1 .. i+6.
#pragma unroll
        for (int c = 0; c < 14; c++) {
            sx[c]  -= xo[c];
            sy[c]  -= yo[c];
            sq[c]   = fmaf(xo[c], -xo[c], sq[c]);
            sq[c]   = fmaf(yo[c], -yo[c], sq[c]);
            sxy[c]  = fmaf(xo[c], -yo[c], sxy[c]);
        }
    }

    // Warp reduce -> one double atomic per warp, spread over 64 slots.
    float al, ah; upk(acc2, al, ah);
    float acc = al + ah;
#pragma unroll
    for (int o = 16; o > 0; o >>= 1)
        acc += __shfl_down_sync(0xFFFFFFFFu, acc, o);
    if (lane == 0)
        atomicAdd(&g_slots[b & (NSLOT - 1)], (double)acc);
}

__global__ void ssim_finalize_kernel(float* __restrict__ out, int out_size) {
    const int t = threadIdx.x;   // 64 threads
    __shared__ double sh[NSLOT];
    double v = g_slots[t];
    sh[t] = v;
    g_slots[t] = 0.0;            // self-reset for next graph replay
    __syncthreads();
    if (t == 0) {
        double s = 0.0;
#pragma unroll
        for (int i = 0; i < NSLOT; i++) s += sh[i];
        float loss = (float)(1.0 - s * (1.0 / NPIX));
        for (int k = 0; k < out_size; k++) out[k] = loss;
    }
}

extern "C" void kernel_launch(void* const* d_in, const int* in_sizes, int n_in,
                              void* d_out, int out_size) {
    const float* X = nullptr;
    const float* Y = nullptr;
    for (int i = 0; i < n_in; i++) {
        if (in_sizes[i] == 4 * 64 * 256 * 256) {
            if (!X) X = (const float*)d_in[i];
            else if (!Y) Y = (const float*)d_in[i];
        }
    }

    ssim_main_kernel<<<NCTA, 32>>>(X, Y);
    ssim_finalize_kernel<<<1, NSLOT>>>((float*)d_out, out_size);
}

// round 4
// speedup vs baseline: 1.1101x; 1.0122x over previous
#include <cuda_runtime.h>

// SSIM loss: X,Y (4,64,256,256) fp32, 7x7 valid box, loss scalar -> out[4].
// loss = 1 - mean(S) over all (B*D, 250, 250) pixels.
//
// Scale-folded formula (49^4 cancels): with H* = raw 7x7 window sums,
//   A1 = 2*Hx*Hy + c1                    c1 = 49^2 * 1e-4
//   A2 = covn2*(49*Hxy - Hx*Hy) + c2     c2 = 49^2 * 9e-4, covn2 = 2*49/48
//   B1 = Hx^2 + Hy^2 + c1
//   B2 = covn*(49*Hq - Hx^2 - Hy^2) + c2 (Hq = window sum of x^2+y^2)
//   S  = A1*A2 / (B1*B2)

#define WIN 7
#define HH 256
#define WW 256
#define OUTD 250
#define NSLICES 256          // B*D
#define BANDS 10             // 10 bands * 25 rows = 250 output rows
#define RPB 25
#define NCTA (NSLICES * BANDS)   // 2560 single-warp CTAs (17.3/SM)
#define NSLOT 64
#define NPIX 16000000.0

__device__ double   g_slots[NSLOT];   // zero-init; last CTA self-resets
__device__ unsigned g_ticket = 0;     // last-CTA election; self-resets

typedef unsigned long long u64;

// ---- f32x2 packed helpers (fma pipe, 2 floats per issue slot) ----
__device__ __forceinline__ u64 pk(float lo, float hi) {
    u64 r; asm("mov.b64 %0, {%1,%2};" : "=l"(r) : "f"(lo), "f"(hi)); return r;
}
__device__ __forceinline__ void upk(u64 v, float& lo, float& hi) {
    asm("mov.b64 {%0,%1}, %2;" : "=f"(lo), "=f"(hi) : "l"(v));
}
__device__ __forceinline__ u64 f2add(u64 a, u64 b) {
    u64 d; asm("add.rn.f32x2 %0,%1,%2;" : "=l"(d) : "l"(a), "l"(b)); return d;
}
__device__ __forceinline__ u64 f2mul(u64 a, u64 b) {
    u64 d; asm("mul.rn.f32x2 %0,%1,%2;" : "=l"(d) : "l"(a), "l"(b)); return d;
}
__device__ __forceinline__ u64 f2fma(u64 a, u64 b, u64 c) {
    u64 d; asm("fma.rn.f32x2 %0,%1,%2,%3;" : "=l"(d) : "l"(a), "l"(b), "l"(c)); return d;
}

// Load 16 consecutive floats (4x float4) starting at col0 of row pointer p.
// Chunks with col >= 256 become zeros (consumed only by masked outputs).
__device__ __forceinline__ void load16(const float* __restrict__ p, int col0, float v[16]) {
#pragma unroll
    for (int k = 0; k < 4; k++) {
        int col = col0 + 4 * k;
        float4 a = make_float4(0.f, 0.f, 0.f, 0.f);
        if (col < WW) a = *reinterpret_cast<const float4*>(p + col);
        v[4 * k + 0] = a.x; v[4 * k + 1] = a.y;
        v[4 * k + 2] = a.z; v[4 * k + 3] = a.w;
    }
}

__global__ void __launch_bounds__(32) ssim_main_kernel(
        const float* __restrict__ X, const float* __restrict__ Y,
        float* __restrict__ out, int out_size) {
    const int b     = blockIdx.x;
    const int lane  = threadIdx.x;
    const int slice = b / BANDS;
    const int band  = b % BANDS;

    const float* xs = X + (size_t)slice * (HH * WW);
    const float* ys = Y + (size_t)slice * (HH * WW);
    const int cb = lane * 8;          // first output column owned by this lane

    // Packed constants
    const float c1f  = 49.0f * 49.0f * 1e-4f;
    const float c2f  = 49.0f * 49.0f * 9e-4f;
    const float covn = 49.0f / 48.0f;
    const u64 C1V    = pk(c1f, c1f);
    const u64 C2V    = pk(c2f, c2f);
    const u64 TWOV   = pk(2.0f, 2.0f);
    const u64 NCV2   = pk(-2.0f * covn, -2.0f * covn);
    const u64 CV2_49 = pk(98.0f * covn, 98.0f * covn);
    const u64 NCV    = pk(-covn, -covn);
    const u64 CV_49  = pk(49.0f * covn, 49.0f * covn);

    // Validity masks per output pair (only lane 31 has invalid columns)
    u64 mask[4];
#pragma unroll
    for (int jp = 0; jp < 4; jp++) {
        float m0 = (cb + 2 * jp     < OUTD) ? 1.0f : 0.0f;
        float m1 = (cb + 2 * jp + 1 < OUTD) ? 1.0f : 0.0f;
        mask[jp] = pk(m0, m1);
    }

    // Vertical sliding 7-row sums for 14 columns, in registers.
    float sx[14], sy[14], sq[14], sxy[14];
#pragma unroll
    for (int c = 0; c < 14; c++) { sx[c] = 0.f; sy[c] = 0.f; sq[c] = 0.f; sxy[c] = 0.f; }

    const int r0 = band * RPB;

    // Prologue: rows r0 .. r0+5
    for (int r = r0; r < r0 + WIN - 1; ++r) {
        float xv[16], yv[16];
        load16(xs + r * WW, cb, xv);
        load16(ys + r * WW, cb, yv);
#pragma unroll
        for (int c = 0; c < 14; c++) {
            float x = xv[c], y = yv[c];
            sx[c] += x; sy[c] += y;
            sq[c]  = fmaf(x, x, sq[c]);
            sq[c]  = fmaf(y, y, sq[c]);
            sxy[c] = fmaf(x, y, sxy[c]);
        }
    }

    u64 acc2 = pk(0.f, 0.f);

    for (int i = r0; i < r0 + RPB; ++i) {
        float xn[16], yn[16];
        load16(xs + (i + 6) * WW, cb, xn);       // entering row i+6 (DRAM)
        load16(ys + (i + 6) * WW, cb, yn);

        // Add entering row: window = rows i .. i+6.
#pragma unroll
        for (int c = 0; c < 14; c++) {
            sx[c]  += xn[c];
            sy[c]  += yn[c];
            sq[c]   = fmaf(xn[c], xn[c], sq[c]);
            sq[c]   = fmaf(yn[c], yn[c], sq[c]);
            sxy[c]  = fmaf(xn[c], yn[c], sxy[c]);
        }

        // Horizontal sliding 7-sum, outputs in packed pairs.
        float hx = 0.f, hy = 0.f, hq = 0.f, hxy = 0.f;
#pragma unroll
        for (int c = 0; c < 6; c++) { hx += sx[c]; hy += sy[c]; hq += sq[c]; hxy += sxy[c]; }

#pragma unroll
        for (int jp = 0; jp < 4; jp++) {
            const int j0 = 2 * jp;
            hx += sx[j0 + 6]; hy += sy[j0 + 6]; hq += sq[j0 + 6]; hxy += sxy[j0 + 6];
            const float hx0 = hx, hy0 = hy, hq0 = hq, hxy0 = hxy;
            hx += sx[j0 + 7] - sx[j0];
            hy += sy[j0 + 7] - sy[j0];
            hq += sq[j0 + 7] - sq[j0];
            hxy += sxy[j0 + 7] - sxy[j0];

            u64 Hx  = pk(hx0,  hx);
            u64 Hy  = pk(hy0,  hy);
            u64 Hq  = pk(hq0,  hq);
            u64 Hxy = pk(hxy0, hxy);

            u64 P   = f2mul(Hx, Hy);
            u64 A1  = f2fma(TWOV,   P,  C1V);
            u64 T   = f2fma(NCV2,   P,  C2V);
            u64 A2  = f2fma(CV2_49, Hxy, T);
            u64 Q   = f2mul(Hy, Hy);
            u64 S2  = f2fma(Hx, Hx, Q);
            u64 B1  = f2add(S2, C1V);
            u64 U   = f2fma(NCV,   S2, C2V);
            u64 B2  = f2fma(CV_49, Hq, U);
            u64 num = f2mul(A1, A2);
            num     = f2mul(num, mask[jp]);
            u64 den = f2mul(B1, B2);             // > 0 always

            // Packed Newton reciprocal (2 iters)
            float dl, dh; upk(den, dl, dh);
            unsigned bl = __float_as_uint(dl), bh = __float_as_uint(dh);
            u64 r  = pk(__uint_as_float(0x7EF311C3u - bl),
                        __uint_as_float(0x7EF311C3u - bh));
            u64 nd = pk(__uint_as_float(bl ^ 0x80000000u),
                        __uint_as_float(bh ^ 0x80000000u));
            u64 t  = f2fma(nd, r, TWOV); r = f2mul(r, t);
            t      = f2fma(nd, r, TWOV); r = f2mul(r, t);

            acc2 = f2fma(num, r, acc2);

            hx -= sx[j0 + 1]; hy -= sy[j0 + 1]; hq -= sq[j0 + 1]; hxy -= sxy[j0 + 1];
        }

        // Leaving row loaded LATE (L1/L2 hit) to keep register pressure down.
        float xo[16], yo[16];
        load16(xs + i * WW, cb, xo);
        load16(ys + i * WW, cb, yo);
#pragma unroll
        for (int c = 0; c < 14; c++) {
            sx[c]  -= xo[c];
            sy[c]  -= yo[c];
            sq[c]   = fmaf(xo[c], -xo[c], sq[c]);
            sq[c]   = fmaf(yo[c], -yo[c], sq[c]);
            sxy[c]  = fmaf(xo[c], -yo[c], sxy[c]);
        }
    }

    // Warp reduce -> one double atomic per CTA, spread over 64 slots.
    float al, ah; upk(acc2, al, ah);
    float acc = al + ah;
#pragma unroll
    for (int o = 16; o > 0; o >>= 1)
        acc += __shfl_down_sync(0xFFFFFFFFu, acc, o);
    if (lane == 0)
        atomicAdd(&g_slots[b & (NSLOT - 1)], (double)acc);

    // ---- Fused finalize: last CTA computes loss and writes out ----
    __threadfence();
    unsigned ticket = 0xFFFFFFFFu;
    if (lane == 0) ticket = atomicInc(&g_ticket, 0xFFFFFFFFu);
    ticket = __shfl_sync(0xFFFFFFFFu, ticket, 0);
    if (ticket == NCTA - 1) {
        __threadfence();                        // acquire all slot updates
        double v = g_slots[lane] + g_slots[lane + 32];
        g_slots[lane] = 0.0;                    // reset for next replay
        g_slots[lane + 32] = 0.0;
#pragma unroll
        for (int o = 16; o > 0; o >>= 1)
            v += __shfl_down_sync(0xFFFFFFFFu, v, o);
        if (lane == 0) {
            float loss = (float)(1.0 - v * (1.0 / NPIX));
            for (int k = 0; k < out_size; k++) out[k] = loss;
            g_ticket = 0;                       // reset for next replay
        }
    }
}

extern "C" void kernel_launch(void* const* d_in, const int* in_sizes, int n_in,
                              void* d_out, int out_size) {
    const float* X = nullptr;
    const float* Y = nullptr;
    for (int i = 0; i < n_in; i++) {
        if (in_sizes[i] == 4 * 64 * 256 * 256) {
            if (!X) X = (const float*)d_in[i];
            else if (!Y) Y = (const float*)d_in[i];
        }
    }
    ssim_main_kernel<<<NCTA, 32>>>(X, Y, (float*)d_out, out_size);
}

// round 5
// speedup vs baseline: 1.6550x; 1.4909x over previous
#include <cuda_runtime.h>

// SSIM loss: X,Y (4,64,256,256) fp32, 7x7 valid box, loss scalar -> out[4].
// loss = 1 - mean(S) over all (B*D, 250, 250) pixels.
//
// Scale-folded formula (49^4 cancels): with H* = raw 7x7 window sums,
//   A1 = 2*Hx*Hy + c1                    c1 = 49^2 * 1e-4
//   A2 = covn2*(49*Hxy - Hx*Hy) + c2     c2 = 49^2 * 9e-4, covn2 = 2*49/48
//   B1 = Hx^2 + Hy^2 + c1
//   B2 = covn*(49*Hq - Hx^2 - Hy^2) + c2 (Hq = window sum of x^2+y^2)
//   S  = A1*A2 / (B1*B2)
//
// Ownership: lane owns cols [8*lane, 8*lane+8) exclusively (coalesced float4
// loads, no overlap). Neighbor col-sums for the horizontal window via SHFL.

#define WIN 7
#define HH 256
#define WW 256
#define OUTD 250
#define NSLICES 256
#define BANDS 10
#define RPB 25
#define NCTA (NSLICES * BANDS)   // 2560 single-warp CTAs
#define NSLOT 64
#define NPIX 16000000.0

__device__ double   g_slots[NSLOT];   // zero-init; last CTA self-resets
__device__ unsigned g_ticket = 0;     // last-CTA election; self-resets

typedef unsigned long long u64;

// ---- f32x2 packed helpers (fma pipe, 2 floats per issue slot) ----
__device__ __forceinline__ u64 pk(float lo, float hi) {
    u64 r; asm("mov.b64 %0, {%1,%2};" : "=l"(r) : "f"(lo), "f"(hi)); return r;
}
__device__ __forceinline__ void upk(u64 v, float& lo, float& hi) {
    asm("mov.b64 {%0,%1}, %2;" : "=f"(lo), "=f"(hi) : "l"(v));
}
__device__ __forceinline__ u64 f2add(u64 a, u64 b) {
    u64 d; asm("add.rn.f32x2 %0,%1,%2;" : "=l"(d) : "l"(a), "l"(b)); return d;
}
__device__ __forceinline__ u64 f2sub(u64 a, u64 b) {
    u64 d; asm("sub.rn.f32x2 %0,%1,%2;" : "=l"(d) : "l"(a), "l"(b)); return d;
}
__device__ __forceinline__ u64 f2mul(u64 a, u64 b) {
    u64 d; asm("mul.rn.f32x2 %0,%1,%2;" : "=l"(d) : "l"(a), "l"(b)); return d;
}
__device__ __forceinline__ u64 f2fma(u64 a, u64 b, u64 c) {
    u64 d; asm("fma.rn.f32x2 %0,%1,%2,%3;" : "=l"(d) : "l"(a), "l"(b), "l"(c)); return d;
}

__device__ __forceinline__ u64 shfl_down1_u64(u64 v) {
    float lo, hi; upk(v, lo, hi);
    lo = __shfl_down_sync(0xFFFFFFFFu, lo, 1);
    hi = __shfl_down_sync(0xFFFFFFFFu, hi, 1);
    return pk(lo, hi);
}

// From packed col-sums F[0..3] (own cols 0..7), build 7-wide window sums
// W[m] = (win(2m), win(2m+1)) for 8 outputs, pulling cols 8..13 from lane+1.
// Lane 31: shuffled values are self-clamped garbage; only its W[0] (outputs
// 248,249) avoids them, the rest are masked by the caller.
__device__ __forceinline__ void horiz4(const u64 F[4], u64 W[4]) {
    float s[14];
    upk(F[0], s[0], s[1]); upk(F[1], s[2], s[3]);
    upk(F[2], s[4], s[5]); upk(F[3], s[6], s[7]);
#pragma unroll
    for (int k = 0; k < 3; k++) {
        u64 g = shfl_down1_u64(F[k]);
        upk(g, s[8 + 2 * k], s[9 + 2 * k]);
    }
    float P[14];
    P[0] = s[0];
#pragma unroll
    for (int k = 1; k < 14; k++) P[k] = P[k - 1] + s[k];
    W[0] = f2sub(pk(P[6],  P[7]),  pk(0.0f,  P[0]));
    W[1] = f2sub(pk(P[8],  P[9]),  pk(P[1],  P[2]));
    W[2] = f2sub(pk(P[10], P[11]), pk(P[3],  P[4]));
    W[3] = f2sub(pk(P[12], P[13]), pk(P[5],  P[6]));
}

__global__ void __launch_bounds__(32, 20) ssim_main_kernel(
        const float* __restrict__ X, const float* __restrict__ Y,
        float* __restrict__ out, int out_size) {
    const int b     = blockIdx.x;
    const int lane  = threadIdx.x;
    const int slice = b / BANDS;
    const int band  = b % BANDS;

    // Row r, lane chunk k (k=0,1): xr[r*64 + k]; lane offset = lane*2 float4s.
    const float4* xr = (const float4*)(X + (size_t)slice * (HH * WW)) + lane * 2;
    const float4* yr = (const float4*)(Y + (size_t)slice * (HH * WW)) + lane * 2;

    // Packed constants
    const float covn = 49.0f / 48.0f;
    const u64 C1V    = pk(0.2401f, 0.2401f);            // 49^2 * 1e-4
    const u64 C2V    = pk(2.1609f, 2.1609f);            // 49^2 * 9e-4
    const u64 TWOV   = pk(2.0f, 2.0f);
    const u64 HALFV  = pk(0.5f, 0.5f);
    const u64 NCV2   = pk(-2.0f * covn, -2.0f * covn);
    const u64 CV2_49 = pk(98.0f * covn, 98.0f * covn);
    const u64 NCV    = pk(-covn, -covn);
    const u64 CV_49  = pk(49.0f * covn, 49.0f * covn);
    // Lane 31 outputs 250..255 (pairs 1..3) invalid; pair 0 (248,249) valid.
    const u64 edgemask = (lane == 31) ? pk(0.0f, 0.0f) : pk(1.0f, 1.0f);

    // Packed vertical sliding sums over own 8 cols.
    u64 sx2[4], sy2[4], sq2[4], sxy2[4];
#pragma unroll
    for (int p = 0; p < 4; p++) {
        sx2[p] = pk(0.f, 0.f); sy2[p] = pk(0.f, 0.f);
        sq2[p] = pk(0.f, 0.f); sxy2[p] = pk(0.f, 0.f);
    }

    const int r0 = band * RPB;
    u64 acc2 = pk(0.f, 0.f);

    // Prologue: rows r0 .. r0+5 (add-only).
    for (int r = r0; r < r0 + WIN - 1; ++r) {
        float4 a0 = xr[r * 64], a1 = xr[r * 64 + 1];
        float4 b0 = yr[r * 64], b1 = yr[r * 64 + 1];
        float ax[8] = {a0.x, a0.y, a0.z, a0.w, a1.x, a1.y, a1.z, a1.w};
        float ay[8] = {b0.x, b0.y, b0.z, b0.w, b1.x, b1.y, b1.z, b1.w};
#pragma unroll
        for (int p = 0; p < 4; p++) {
            u64 xp = pk(ax[2 * p], ax[2 * p + 1]);
            u64 yp = pk(ay[2 * p], ay[2 * p + 1]);
            sx2[p]  = f2add(sx2[p], xp);
            sy2[p]  = f2add(sy2[p], yp);
            sq2[p]  = f2fma(xp, xp, sq2[p]);
            sq2[p]  = f2fma(yp, yp, sq2[p]);
            sxy2[p] = f2fma(xp, yp, sxy2[p]);
        }
    }

    for (int i = r0; i < r0 + RPB; ++i) {
        // Entering row i+6 (fresh), leaving row i-1 (L1/L2 hit; zeros at i==r0:
        // merged delta update with xo=0 degenerates to pure add).
        float4 a0 = xr[(i + 6) * 64], a1 = xr[(i + 6) * 64 + 1];
        float4 b0 = yr[(i + 6) * 64], b1 = yr[(i + 6) * 64 + 1];
        float4 c0 = make_float4(0.f, 0.f, 0.f, 0.f), c1 = c0, d0 = c0, d1 = c0;
        if (i > r0) {
            c0 = xr[(i - 1) * 64]; c1 = xr[(i - 1) * 64 + 1];
            d0 = yr[(i - 1) * 64]; d1 = yr[(i - 1) * 64 + 1];
        }
        float an[8] = {a0.x, a0.y, a0.z, a0.w, a1.x, a1.y, a1.z, a1.w};
        float bn[8] = {b0.x, b0.y, b0.z, b0.w, b1.x, b1.y, b1.z, b1.w};
        float ao[8] = {c0.x, c0.y, c0.z, c0.w, c1.x, c1.y, c1.z, c1.w};
        float bo[8] = {d0.x, d0.y, d0.z, d0.w, d1.x, d1.y, d1.z, d1.w};

        // Merged add(i+6)/sub(i-1): state becomes window rows i..i+6.
        //   x_n^2 - x_o^2 = dx*(x_n+x_o);  x_n*y_n - x_o*y_o = 0.5*(dx*sy + dy*sx)
#pragma unroll
        for (int p = 0; p < 4; p++) {
            u64 xn = pk(an[2 * p], an[2 * p + 1]);
            u64 yn = pk(bn[2 * p], bn[2 * p + 1]);
            u64 xo = pk(ao[2 * p], ao[2 * p + 1]);
            u64 yo = pk(bo[2 * p], bo[2 * p + 1]);
            u64 dx = f2sub(xn, xo), sxp = f2add(xn, xo);
            u64 dy = f2sub(yn, yo), syp = f2add(yn, yo);
            sx2[p] = f2add(sx2[p], dx);
            sy2[p] = f2add(sy2[p], dy);
            sq2[p] = f2fma(dx, sxp, sq2[p]);
            sq2[p] = f2fma(dy, syp, sq2[p]);
            u64 t  = f2mul(dx, syp);
            t      = f2fma(dy, sxp, t);
            sxy2[p] = f2fma(t, HALFV, sxy2[p]);
        }

        // Horizontal 7-window sums (prefix + packed diffs), 8 outputs/lane.
        u64 Wx[4], Wy[4], Wq[4], Wxy[4];
        horiz4(sx2,  Wx);
        horiz4(sy2,  Wy);
        horiz4(sq2,  Wq);
        horiz4(sxy2, Wxy);

#pragma unroll
        for (int m = 0; m < 4; m++) {
            u64 Hx = Wx[m], Hy = Wy[m], Hq = Wq[m], Hxy = Wxy[m];
            u64 P   = f2mul(Hx, Hy);
            u64 A1  = f2fma(TWOV,   P,   C1V);
            u64 T   = f2fma(NCV2,   P,   C2V);
            u64 A2  = f2fma(CV2_49, Hxy, T);
            u64 Q   = f2mul(Hy, Hy);
            u64 S2  = f2fma(Hx, Hx, Q);
            u64 B1  = f2add(S2, C1V);
            u64 U   = f2fma(NCV,   S2, C2V);
            u64 B2  = f2fma(CV_49, Hq, U);
            u64 num = f2mul(A1, A2);
            if (m > 0) num = f2mul(num, edgemask);   // only lane31 pairs 1..3 invalid
            u64 den = f2mul(B1, B2);                 // > 0 always (Cauchy-Schwarz)

            // Packed Newton reciprocal (2 iters; seed ~3e-2 -> ~1e-6)
            float dl, dh; upk(den, dl, dh);
            unsigned bl = __float_as_uint(dl), bh = __float_as_uint(dh);
            u64 r  = pk(__uint_as_float(0x7EF311C3u - bl),
                        __uint_as_float(0x7EF311C3u - bh));
            u64 nd = pk(__uint_as_float(bl ^ 0x80000000u),
                        __uint_as_float(bh ^ 0x80000000u));
            u64 t2 = f2fma(nd, r, TWOV); r = f2mul(r, t2);
            t2     = f2fma(nd, r, TWOV); r = f2mul(r, t2);

            acc2 = f2fma(num, r, acc2);
        }
    }

    // Warp reduce -> one double atomic per CTA, spread over 64 slots.
    float al, ah; upk(acc2, al, ah);
    float acc = al + ah;
#pragma unroll
    for (int o = 16; o > 0; o >>= 1)
        acc += __shfl_down_sync(0xFFFFFFFFu, acc, o);
    if (lane == 0)
        atomicAdd(&g_slots[b & (NSLOT - 1)], (double)acc);

    // ---- Fused finalize: last CTA computes loss and writes out ----
    __threadfence();
    unsigned ticket = 0xFFFFFFFFu;
    if (lane == 0) ticket = atomicInc(&g_ticket, 0xFFFFFFFFu);
    ticket = __shfl_sync(0xFFFFFFFFu, ticket, 0);
    if (ticket == NCTA - 1) {
        __threadfence();
        double v = g_slots[lane] + g_slots[lane + 32];
        g_slots[lane] = 0.0;
        g_slots[lane + 32] = 0.0;
#pragma unroll
        for (int o = 16; o > 0; o >>= 1)
            v += __shfl_down_sync(0xFFFFFFFFu, v, o);
        if (lane == 0) {
            float loss = (float)(1.0 - v * (1.0 / NPIX));
            for (int k = 0; k < out_size; k++) out[k] = loss;
            g_ticket = 0;
        }
    }
}

extern "C" void kernel_launch(void* const* d_in, const int* in_sizes, int n_in,
                              void* d_out, int out_size) {
    const float* X = nullptr;
    const float* Y = nullptr;
    for (int i = 0; i < n_in; i++) {
        if (in_sizes[i] == 4 * 64 * 256 * 256) {
            if (!X) X = (const float*)d_in[i];
            else if (!Y) Y = (const float*)d_in[i];
        }
    }
    ssim_main_kernel<<<NCTA, 32>>>(X, Y, (float*)d_out, out_size);
}

// round 6
// speedup vs baseline: 1.9237x; 1.1623x over previous
#include <cuda_runtime.h>

// SSIM loss: X,Y (4,64,256,256) fp32, 7x7 valid box, loss scalar -> out[4].
// loss = 1 - mean(S) over all (B*D, 250, 250) pixels.
//
// Scale-folded formula (49^4 cancels): with H* = raw 7x7 window sums,
//   A1 = 2*Hx*Hy + c1                    c1 = 49^2*1e-4
//   A2 = 2c*(49*Hxy - Hx*Hy) + c2        c2 = 49^2*9e-4,  c = 49/48
//   B1 = Hx^2 + Hy^2 + c1
//   B2 = c*(49*Hq - Hx^2 - Hy^2) + c2    (Hq = window sum of x^2+y^2)
//   S  = A1*A2 / (B1*B2)
//
// Lane owns cols [8L,8L+8) (coalesced 16B loads). Neighbor col-sums via SHFL.
// Loop is phase-shifted: emit outputs for window(i) BEFORE applying the
// vertical update with rows prefetched one full iteration earlier.

#define WIN 7
#define HH 256
#define WW 256
#define OUTD 250
#define NSLICES 256
#define BANDS 9              // 8 bands of 28 rows + 1 of 26
#define RPBMAX 28
#define NCTA (NSLICES * BANDS)   // 2304 single-warp CTAs: one wave @16/SM
#define NSLOT 64
#define NPIX 16000000.0

__device__ double   g_slots[NSLOT];   // zero-init; last CTA self-resets
__device__ unsigned g_ticket = 0;

typedef unsigned long long u64;

// ---- f32x2 packed helpers ----
__device__ __forceinline__ u64 pk(float lo, float hi) {
    u64 r; asm("mov.b64 %0, {%1,%2};" : "=l"(r) : "f"(lo), "f"(hi)); return r;
}
__device__ __forceinline__ void upk(u64 v, float& lo, float& hi) {
    asm("mov.b64 {%0,%1}, %2;" : "=f"(lo), "=f"(hi) : "l"(v));
}
__device__ __forceinline__ u64 f2add(u64 a, u64 b) {
    u64 d; asm("add.rn.f32x2 %0,%1,%2;" : "=l"(d) : "l"(a), "l"(b)); return d;
}
__device__ __forceinline__ u64 f2sub(u64 a, u64 b) {
    u64 d; asm("sub.rn.f32x2 %0,%1,%2;" : "=l"(d) : "l"(a), "l"(b)); return d;
}
__device__ __forceinline__ u64 f2mul(u64 a, u64 b) {
    u64 d; asm("mul.rn.f32x2 %0,%1,%2;" : "=l"(d) : "l"(a), "l"(b)); return d;
}
__device__ __forceinline__ u64 f2fma(u64 a, u64 b, u64 c) {
    u64 d; asm("fma.rn.f32x2 %0,%1,%2,%3;" : "=l"(d) : "l"(a), "l"(b), "l"(c)); return d;
}

// Horizontal 7-window sums from packed col-sums F[0..3] (own cols 0..7) and
// lane+1's leading 6 cols (via shuffle). W[m] = (win(2m), win(2m+1)).
// Lane 31: shuffled values are self-garbage; only W[0] (outputs 248,249)
// avoids them — the rest are masked by the caller.
__device__ __forceinline__ void horiz(const u64 F[4], u64 W[4]) {
    float s[14];
    upk(F[0], s[0], s[1]); upk(F[1], s[2], s[3]);
    upk(F[2], s[4], s[5]); upk(F[3], s[6], s[7]);
    u64 g0 = __shfl_down_sync(0xFFFFFFFFu, F[0], 1);
    u64 g1 = __shfl_down_sync(0xFFFFFFFFu, F[1], 1);
    u64 g2 = __shfl_down_sync(0xFFFFFFFFu, F[2], 1);
    upk(g0, s[8], s[9]); upk(g1, s[10], s[11]); upk(g2, s[12], s[13]);
    float P[14];
    P[0] = s[0];
#pragma unroll
    for (int k = 1; k < 14; k++) P[k] = P[k - 1] + s[k];
    W[0] = f2sub(pk(P[6],  P[7]),  pk(0.0f,  P[0]));
    W[1] = f2sub(pk(P[8],  P[9]),  pk(P[1],  P[2]));
    W[2] = f2sub(pk(P[10], P[11]), pk(P[3],  P[4]));
    W[3] = f2sub(pk(P[12], P[13]), pk(P[5],  P[6]));
}

__global__ void __launch_bounds__(32, 16) ssim_main_kernel(
        const float* __restrict__ X, const float* __restrict__ Y,
        float* __restrict__ out, int out_size) {
    const int b     = blockIdx.x;
    const int lane  = threadIdx.x;
    const int slice = b / BANDS;
    const int band  = b % BANDS;

    // Row stride = 64 ulonglong2 (256 floats); lane offset = 2 (8 floats).
    const ulonglong2* xr = (const ulonglong2*)(X + (size_t)slice * (HH * WW)) + lane * 2;
    const ulonglong2* yr = (const ulonglong2*)(Y + (size_t)slice * (HH * WW)) + lane * 2;

    const float covn = 49.0f / 48.0f;
    const u64 C1V    = pk(0.2401f, 0.2401f);
    const u64 C2V    = pk(2.1609f, 2.1609f);
    const u64 TWOV   = pk(2.0f, 2.0f);
    const u64 HALFV  = pk(0.5f, 0.5f);
    const u64 NEG1V  = pk(-1.0f, -1.0f);
    const u64 NCV2   = pk(-2.0f * covn, -2.0f * covn);
    const u64 CV2_49 = pk(98.0f * covn, 98.0f * covn);
    const u64 NCV    = pk(-covn, -covn);
    const u64 CV_49  = pk(49.0f * covn, 49.0f * covn);
    const u64 edgemask = (lane == 31) ? pk(0.0f, 0.0f) : pk(1.0f, 1.0f);

    u64 sx2[4], sy2[4], sq2[4], sxy2[4];
#pragma unroll
    for (int p = 0; p < 4; p++) {
        sx2[p] = pk(0.f, 0.f); sy2[p] = pk(0.f, 0.f);
        sq2[p] = pk(0.f, 0.f); sxy2[p] = pk(0.f, 0.f);
    }

    const int r0    = band * RPBMAX;
    const int nrows = (250 - r0 < RPBMAX) ? (250 - r0) : RPBMAX;

    // Prologue: full first window, rows r0 .. r0+6 (7 rows).
    for (int r = r0; r < r0 + WIN; ++r) {
        ulonglong2 xa = xr[r * 64], xb = xr[r * 64 + 1];
        ulonglong2 ya = yr[r * 64], yb = yr[r * 64 + 1];
        u64 xv[4] = {xa.x, xa.y, xb.x, xb.y};
        u64 yv[4] = {ya.x, ya.y, yb.x, yb.y};
#pragma unroll
        for (int p = 0; p < 4; p++) {
            sx2[p]  = f2add(sx2[p], xv[p]);
            sy2[p]  = f2add(sy2[p], yv[p]);
            sq2[p]  = f2fma(xv[p], xv[p], sq2[p]);
            sq2[p]  = f2fma(yv[p], yv[p], sq2[p]);
            sxy2[p] = f2fma(xv[p], yv[p], sxy2[p]);
        }
    }

    // Prefetch: entering row r0+7, leaving row r0.
    ulonglong2 nxa = xr[(r0 + 7) * 64], nxb = xr[(r0 + 7) * 64 + 1];
    ulonglong2 nya = yr[(r0 + 7) * 64], nyb = yr[(r0 + 7) * 64 + 1];
    ulonglong2 oxa = xr[r0 * 64],       oxb = xr[r0 * 64 + 1];
    ulonglong2 oya = yr[r0 * 64],       oyb = yr[r0 * 64 + 1];

    u64 acc2 = pk(0.f, 0.f);

    for (int i = r0; i < r0 + nrows; ++i) {
        // ---- Emit outputs for window(i) (state holds rows i..i+6) ----
        u64 Wx[4], Wy[4], Wq[4], Wxy[4];
        horiz(sx2,  Wx);
        horiz(sy2,  Wy);
        horiz(sq2,  Wq);
        horiz(sxy2, Wxy);

        u64 num[4], den[4];
#pragma unroll
        for (int m = 0; m < 4; m++) {
            u64 Hx = Wx[m], Hy = Wy[m], Hq = Wq[m], Hxy = Wxy[m];
            u64 Pp = f2mul(Hx, Hy);
            u64 A1 = f2fma(TWOV,   Pp,  C1V);
            u64 T  = f2fma(NCV2,   Pp,  C2V);
            u64 A2 = f2fma(CV2_49, Hxy, T);
            u64 S2 = f2fma(Hx, Hx, f2mul(Hy, Hy));
            u64 B1 = f2add(S2, C1V);
            u64 U  = f2fma(NCV,   S2, C2V);
            u64 B2 = f2fma(CV_49, Hq, U);
            u64 N  = f2mul(A1, A2);
            if (m > 0) N = f2mul(N, edgemask);
            num[m] = N;
            den[m] = f2mul(B1, B2);          // > 0 always (Cauchy-Schwarz)
        }
        // Merge 4 packed fractions -> one: (na/da + nb/db) = (na*db+nb*da)/(da*db)
        u64 na = f2fma(num[1], den[0], f2mul(num[0], den[1]));
        u64 da = f2mul(den[0], den[1]);
        u64 nb = f2fma(num[3], den[2], f2mul(num[2], den[3]));
        u64 db = f2mul(den[2], den[3]);
        u64 N  = f2fma(nb, da, f2mul(na, db));
        u64 D  = f2mul(da, db);              // <= ~3e29, >= ~0.07: safe in fp32

        // One packed Newton reciprocal per row (seed ~5e-2 -> ~1e-6 after 2 iters)
        float dl, dh; upk(D, dl, dh);
        u64 r = pk(__uint_as_float(0x7EF311C3u - __float_as_uint(dl)),
                   __uint_as_float(0x7EF311C3u - __float_as_uint(dh)));
        u64 ndv = f2mul(D, NEG1V);
        u64 t = f2fma(ndv, r, TWOV); r = f2mul(r, t);
        t     = f2fma(ndv, r, TWOV); r = f2mul(r, t);
        acc2  = f2fma(N, r, acc2);

        // ---- Advance state to window(i+1) with prefetched rows ----
        u64 xn[4] = {nxa.x, nxa.y, nxb.x, nxb.y};
        u64 yn[4] = {nya.x, nya.y, nyb.x, nyb.y};
        u64 xo[4] = {oxa.x, oxa.y, oxb.x, oxb.y};
        u64 yo[4] = {oya.x, oya.y, oyb.x, oyb.y};

        // Prefetch for next iteration: entering row i+8 (clamped), leaving row i+1.
        int nr = i + 8; if (nr > HH - 1) nr = HH - 1;
        nxa = xr[nr * 64];       nxb = xr[nr * 64 + 1];
        nya = yr[nr * 64];       nyb = yr[nr * 64 + 1];
        oxa = xr[(i + 1) * 64];  oxb = xr[(i + 1) * 64 + 1];
        oya = yr[(i + 1) * 64];  oyb = yr[(i + 1) * 64 + 1];

        // Merged delta update: x_n^2-x_o^2 = dx*(x_n+x_o);
        // x_n*y_n - x_o*y_o = 0.5*(dx*(y_n+y_o) + dy*(x_n+x_o))
#pragma unroll
        for (int p = 0; p < 4; p++) {
            u64 dx  = f2sub(xn[p], xo[p]), sxp = f2add(xn[p], xo[p]);
            u64 dy  = f2sub(yn[p], yo[p]), syp = f2add(yn[p], yo[p]);
            sx2[p]  = f2add(sx2[p], dx);
            sy2[p]  = f2add(sy2[p], dy);
            sq2[p]  = f2fma(dx, sxp, sq2[p]);
            sq2[p]  = f2fma(dy, syp, sq2[p]);
            u64 tt  = f2mul(dx, syp);
            tt      = f2fma(dy, sxp, tt);
            sxy2[p] = f2fma(tt, HALFV, sxy2[p]);
        }
    }

    // Warp reduce -> one double atomic per CTA, spread over 64 slots.
    float al, ah; upk(acc2, al, ah);
    float acc = al + ah;
#pragma unroll
    for (int o = 16; o > 0; o >>= 1)
        acc += __shfl_down_sync(0xFFFFFFFFu, acc, o);
    if (lane == 0)
        atomicAdd(&g_slots[b & (NSLOT - 1)], (double)acc);

    // ---- Fused finalize: last CTA computes loss and writes out ----
    __threadfence();
    unsigned ticket = 0xFFFFFFFFu;
    if (lane == 0) ticket = atomicInc(&g_ticket, 0xFFFFFFFFu);
    ticket = __shfl_sync(0xFFFFFFFFu, ticket, 0);
    if (ticket == NCTA - 1) {
        __threadfence();
        double v = g_slots[lane] + g_slots[lane + 32];
        g_slots[lane] = 0.0;
        g_slots[lane + 32] = 0.0;
#pragma unroll
        for (int o = 16; o > 0; o >>= 1)
            v += __shfl_down_sync(0xFFFFFFFFu, v, o);
        if (lane == 0) {
            float loss = (float)(1.0 - v * (1.0 / NPIX));
            for (int k = 0; k < out_size; k++) out[k] = loss;
            g_ticket = 0;
        }
    }
}

extern "C" void kernel_launch(void* const* d_in, const int* in_sizes, int n_in,
                              void* d_out, int out_size) {
    const float* X = nullptr;
    const float* Y = nullptr;
    for (int i = 0; i < n_in; i++) {
        if (in_sizes[i] == 4 * 64 * 256 * 256) {
            if (!X) X = (const float*)d_in[i];
            else if (!Y) Y = (const float*)d_in[i];
        }
    }
    ssim_main_kernel<<<NCTA, 32>>>(X, Y, (float*)d_out, out_size);
}